// round 6
// baseline (speedup 1.0000x reference)
#include <cuda_runtime.h>
#include <math.h>

#define B_ 8
#define T_ 1024
#define D_ 512
#define H_ 8
#define BT_ (B_*T_)        /* 8192  */
#define BHT_ (B_*H_*T_)    /* 65536 */

// ---------------- scratch (static device arrays: the sanctioned no-alloc workaround) ----
__device__ float g_Q128[(size_t)BHT_*128];
__device__ float g_K128[(size_t)BHT_*128];
__device__ float g_rq[BHT_];
__device__ float g_rk[BHT_];
__device__ float g_vm[(size_t)BHT_*64];
__device__ float g_vc[(size_t)BHT_*64];
__device__ float g_om[(size_t)BT_*D_];
__device__ float g_oc[(size_t)BT_*D_];

enum { M_PLAIN = 0, M_QKMEAN = 1, M_QKCOV = 2, M_V = 3 };

// ---------------------------------------------------------------------------
// Tiled SGEMM: Y[m,n] = sum_k X[m,k]*W[n,k] + bias[n]
// M=8192, N=512, K=512. BM=BN=64, BK=32, 256 threads, 4x4 per thread.
// Epilogue modes write head-split layouts and per-(b,h,t) row reductions.
// ---------------------------------------------------------------------------
template <int MODE>
__global__ __launch_bounds__(256) void proj_gemm(
    const float* __restrict__ X, const float* __restrict__ W,
    const float* __restrict__ bias, float* __restrict__ out,
    float* __restrict__ rbuf)
{
    __shared__ float Xs[64][33];
    __shared__ float Ws[64][33];

    const int tid = threadIdx.x;
    const int tx = tid & 15, ty = tid >> 4;
    const int m0 = blockIdx.x * 64, n0 = blockIdx.y * 64;

    float acc[4][4];
#pragma unroll
    for (int i = 0; i < 4; i++)
#pragma unroll
        for (int j = 0; j < 4; j++) acc[i][j] = 0.f;

    const int r  = tid >> 2;         // 0..63 : staged row
    const int kk = (tid & 3) * 8;    // 0,8,16,24 : k-offset inside chunk
    const float* Xp = X + (size_t)(m0 + r) * 512 + kk;
    const float* Wp = W + (size_t)(n0 + r) * 512 + kk;

    for (int k0 = 0; k0 < 512; k0 += 32) {
        float4 x0 = *(const float4*)(Xp + k0);
        float4 x1 = *(const float4*)(Xp + k0 + 4);
        float4 w0 = *(const float4*)(Wp + k0);
        float4 w1 = *(const float4*)(Wp + k0 + 4);
        Xs[r][kk + 0] = x0.x; Xs[r][kk + 1] = x0.y; Xs[r][kk + 2] = x0.z; Xs[r][kk + 3] = x0.w;
        Xs[r][kk + 4] = x1.x; Xs[r][kk + 5] = x1.y; Xs[r][kk + 6] = x1.z; Xs[r][kk + 7] = x1.w;
        Ws[r][kk + 0] = w0.x; Ws[r][kk + 1] = w0.y; Ws[r][kk + 2] = w0.z; Ws[r][kk + 3] = w0.w;
        Ws[r][kk + 4] = w1.x; Ws[r][kk + 5] = w1.y; Ws[r][kk + 6] = w1.z; Ws[r][kk + 7] = w1.w;
        __syncthreads();
#pragma unroll
        for (int k2 = 0; k2 < 32; k2++) {
            float a0 = Xs[ty * 4 + 0][k2];
            float a1 = Xs[ty * 4 + 1][k2];
            float a2 = Xs[ty * 4 + 2][k2];
            float a3 = Xs[ty * 4 + 3][k2];
            float b0 = Ws[tx * 4 + 0][k2];
            float b1 = Ws[tx * 4 + 1][k2];
            float b2 = Ws[tx * 4 + 2][k2];
            float b3 = Ws[tx * 4 + 3][k2];
            acc[0][0] = fmaf(a0, b0, acc[0][0]); acc[0][1] = fmaf(a0, b1, acc[0][1]);
            acc[0][2] = fmaf(a0, b2, acc[0][2]); acc[0][3] = fmaf(a0, b3, acc[0][3]);
            acc[1][0] = fmaf(a1, b0, acc[1][0]); acc[1][1] = fmaf(a1, b1, acc[1][1]);
            acc[1][2] = fmaf(a1, b2, acc[1][2]); acc[1][3] = fmaf(a1, b3, acc[1][3]);
            acc[2][0] = fmaf(a2, b0, acc[2][0]); acc[2][1] = fmaf(a2, b1, acc[2][1]);
            acc[2][2] = fmaf(a2, b2, acc[2][2]); acc[2][3] = fmaf(a2, b3, acc[2][3]);
            acc[3][0] = fmaf(a3, b0, acc[3][0]); acc[3][1] = fmaf(a3, b1, acc[3][1]);
            acc[3][2] = fmaf(a3, b2, acc[3][2]); acc[3][3] = fmaf(a3, b3, acc[3][3]);
        }
        __syncthreads();
    }

    float bs[4];
#pragma unroll
    for (int j = 0; j < 4; j++) bs[j] = bias[n0 + tx * 4 + j];

    float part[4] = {0.f, 0.f, 0.f, 0.f};
    const int head = n0 >> 6;

#pragma unroll
    for (int i = 0; i < 4; i++) {
        const int m = m0 + ty * 4 + i;
        const int b = m >> 10, t = m & 1023;
        const int bh = b * 8 + head;
#pragma unroll
        for (int j = 0; j < 4; j++) {
            const float y = acc[i][j] + bs[j];
            const int cin = tx * 4 + j;
            if (MODE == M_PLAIN) {
                out[(size_t)m * 512 + n0 + cin] = y;
            } else if (MODE == M_V) {
                out[((size_t)bh * 1024 + t) * 64 + cin] = y;
            } else if (MODE == M_QKMEAN) {
                out[((size_t)bh * 1024 + t) * 128 + cin] = y;
                part[i] += y * y;
            } else { // M_QKCOV
                out[((size_t)bh * 1024 + t) * 128 + 64 + cin] = sqrtf(fmaxf(y, 1e-24f));
                part[i] += y;
            }
        }
    }

    if (MODE == M_QKMEAN || MODE == M_QKCOV) {
        __syncthreads();
#pragma unroll
        for (int i = 0; i < 4; i++) Xs[ty * 4 + i][tx] = part[i];
        __syncthreads();
        if (tid < 64) {
            float s = 0.f;
#pragma unroll
            for (int x = 0; x < 16; x++) s += Xs[tid][x];
            const int m = m0 + tid;
            const int b = m >> 10, t = m & 1023;
            const size_t idx = ((size_t)(b * 8 + head)) * 1024 + t;
            if (MODE == M_QKMEAN) rbuf[idx] = s;
            else                  rbuf[idx] += s;
        }
    }
}

// ---------------------------------------------------------------------------
// Attention kernel: warp-per-row, block of 8 consecutive rows sharing staged
// 32x128 K / V tiles. Score row in smem; 5 passes per row.
// grid (64 bh, 128 t-chunks), 256 threads.
// ---------------------------------------------------------------------------
__global__ __launch_bounds__(256) void attn_kernel(const float* __restrict__ gammas,
                                                   const int* __restrict__ zp_ptr)
{
    extern __shared__ float sm[];
    float* sTile = sm;               // 32*129 floats (K tile, later V tile)
    float* sQ    = sm + 32 * 129;    // 8*128
    float* sRow  = sQ + 8 * 128;     // 8*1024

    const int bh  = blockIdx.x;
    const int b   = bh >> 3, h = bh & 7;
    const int wid = threadIdx.x >> 5, lane = threadIdx.x & 31;
    const int t   = blockIdx.y * 8 + wid;
    const int ntiles = ((blockIdx.y * 8 + 7) >> 5) + 1;

    // stage this warp's 128-vector q (only own warp reads it)
    {
        const float* Q = g_Q128 + ((size_t)bh * T_ + t) * 128;
#pragma unroll
        for (int j = 0; j < 4; j++) sQ[wid * 128 + lane + 32 * j] = Q[lane + 32 * j];
    }
    const float rq = g_rq[(size_t)bh * T_ + t];
    const float g  = gammas[h];
    const float sp = (g > 20.f) ? g : log1pf(__expf(g));
    const float gamma = -sp;               // gamma = -softplus(gammas[h]) < 0
    float* row = sRow + wid * 1024;
    __syncwarp();

    // ---- P1: raw scores ---------------------------------------------------
    const float* Kg = g_K128 + (size_t)bh * T_ * 128;
    for (int it = 0; it < ntiles; ++it) {
        const int s0 = it * 32;
        // stage 32 rows x 128 floats (1024 float4s): sr = v>>5, c4 = (v&31)*4
        for (int v = threadIdx.x; v < 1024; v += 256) {
            const int sr = v >> 5, c4 = (v & 31) * 4;
            float4 kv = *(const float4*)(Kg + (size_t)(s0 + sr) * 128 + c4);
            float* d = sTile + sr * 129 + c4;
            d[0] = kv.x; d[1] = kv.y; d[2] = kv.z; d[3] = kv.w;
        }
        __syncthreads();
        if (s0 <= t) {
            const int s = s0 + lane;
            float acc = 0.f;
            const float* qp = sQ + wid * 128;
            const float* kp = sTile + lane * 129;
#pragma unroll
            for (int c = 0; c < 128; c += 4) {
                float4 q4 = *(const float4*)(qp + c);
                acc = fmaf(q4.x, kp[c + 0], acc);
                acc = fmaf(q4.y, kp[c + 1], acc);
                acc = fmaf(q4.z, kp[c + 2], acc);
                acc = fmaf(q4.w, kp[c + 3], acc);
            }
            const float rk = g_rk[(size_t)bh * T_ + s];
            row[s] = (2.f * acc - rq - rk) * 0.125f;   // /sqrt(dk)=8
        }
        __syncthreads();
    }

    // ---- P2: max + sum(exp) of first softmax ------------------------------
    float m1 = -3.4e38f;
    for (int s = lane; s <= t; s += 32) m1 = fmaxf(m1, row[s]);
#pragma unroll
    for (int o = 16; o; o >>= 1) m1 = fmaxf(m1, __shfl_xor_sync(0xffffffffu, m1, o));
    float den1 = 0.f;
    for (int s = lane; s <= t; s += 32) den1 += __expf(row[s] - m1);
#pragma unroll
    for (int o = 16; o; o >>= 1) den1 += __shfl_xor_sync(0xffffffffu, den1, o);
    const float inv1 = 1.f / den1;

    // ---- P3: cumsum + position-decay rescore ------------------------------
    float carry = 0.f, m2 = -3.4e38f;
    for (int s0 = 0; s0 <= t; s0 += 32) {
        const int s = s0 + lane;
        const bool valid = (s <= t);
        const float sc = valid ? row[s] : 0.f;
        const float e  = valid ? __expf(sc - m1) : 0.f;
        float x = e;
#pragma unroll
        for (int d = 1; d < 32; d <<= 1) {
            float y = __shfl_up_sync(0xffffffffu, x, d);
            if (lane >= d) x += y;
        }
        const float tot = __shfl_sync(0xffffffffu, x, 31);
        const float cum = carry + x;
        carry += tot;
        if (valid) {
            const float tail = (den1 - cum) * inv1;          // 1 - cumsum(p)
            const float pos  = (float)(t - s);
            const float dsc  = sqrtf(fmaxf(tail * pos, 0.f));
            float eff = __expf(gamma * dsc);
            eff = fminf(fmaxf(eff, 1e-5f), 1e5f);
            const float ns = sc * eff;
            row[s] = ns;
            m2 = fmaxf(m2, ns);
        }
    }
#pragma unroll
    for (int o = 16; o; o >>= 1) m2 = fmaxf(m2, __shfl_xor_sync(0xffffffffu, m2, o));

    // ---- P4: second softmax denom; store exp in place ----------------------
    float den2 = 0.f;
    for (int s0 = 0; s0 <= t; s0 += 32) {
        const int s = s0 + lane;
        const float e = (s <= t) ? __expf(row[s] - m2) : 0.f;
        row[s] = e;                       // 0 for lanes beyond t
        den2 += e;
    }
#pragma unroll
    for (int o = 16; o; o >>= 1) den2 += __shfl_xor_sync(0xffffffffu, den2, o);
    const float inv2 = 1.f / den2;

    // ---- P5: P*V and P^2*Vc ------------------------------------------------
    float aM0 = 0.f, aM1 = 0.f, aC0 = 0.f, aC1 = 0.f;
    const float* Vm = g_vm + (size_t)bh * T_ * 64;
    const float* Vc = g_vc + (size_t)bh * T_ * 64;
    for (int it = 0; it < ntiles; ++it) {
        const int s0 = it * 32;
        for (int v = threadIdx.x; v < 512; v += 256) {
            const int sr = v >> 4, c4 = (v & 15) * 4;
            float4 a = *(const float4*)(Vm + (size_t)(s0 + sr) * 64 + c4);
            float4 c = *(const float4*)(Vc + (size_t)(s0 + sr) * 64 + c4);
            float* dm = sTile + sr * 129 + c4;
            dm[0] = a.x; dm[1] = a.y; dm[2] = a.z; dm[3] = a.w;
            float* dc = sTile + sr * 129 + 64 + c4;
            dc[0] = c.x; dc[1] = c.y; dc[2] = c.z; dc[3] = c.w;
        }
        __syncthreads();
        if (s0 <= t) {
#pragma unroll 4
            for (int j = 0; j < 32; ++j) {
                const float e  = row[s0 + j];     // broadcast LDS; 0 beyond t
                const float e2 = e * e;
                const float* vp = sTile + j * 129;
                aM0 = fmaf(e,  vp[lane],      aM0);
                aM1 = fmaf(e,  vp[32 + lane], aM1);
                aC0 = fmaf(e2, vp[64 + lane], aC0);
                aC1 = fmaf(e2, vp[96 + lane], aC1);
            }
        }
        __syncthreads();
    }

    float sMean = inv2, sCov = inv2 * inv2;
    if (t == 0 && (*zp_ptr)) { sMean = 0.f; sCov = 0.f; }   // zero_pad
    const size_t ob = ((size_t)b * T_ + t) * 512 + h * 64;
    g_om[ob + lane]      = aM0 * sMean;
    g_om[ob + 32 + lane] = aM1 * sMean;
    g_oc[ob + lane]      = aC0 * sCov;
    g_oc[ob + 32 + lane] = aC1 * sCov;
}

// ---------------------------------------------------------------------------
extern "C" void kernel_launch(void* const* d_in, const int* in_sizes, int n_in,
                              void* d_out, int out_size)
{
    const float* q_mean  = (const float*)d_in[0];
    const float* q_cov   = (const float*)d_in[1];
    const float* k_mean  = (const float*)d_in[2];
    const float* k_cov   = (const float*)d_in[3];
    const float* v_mean  = (const float*)d_in[4];
    const float* v_cov   = (const float*)d_in[5];
    const float* Wk_mean = (const float*)d_in[6];
    const float* bk_mean = (const float*)d_in[7];
    const float* Wk_cov  = (const float*)d_in[8];
    const float* bk_cov  = (const float*)d_in[9];
    const float* Wv_mean = (const float*)d_in[10];
    const float* bv_mean = (const float*)d_in[11];
    const float* Wv_cov  = (const float*)d_in[12];
    const float* bv_cov  = (const float*)d_in[13];
    const float* Wo_mean = (const float*)d_in[14];
    const float* bo_mean = (const float*)d_in[15];
    const float* Wo_cov  = (const float*)d_in[16];
    const float* bo_cov  = (const float*)d_in[17];
    const float* gammas  = (const float*)d_in[18];
    const int*   zp      = (const int*)d_in[20];
    float* out = (float*)d_out;

    float *Q128, *K128, *rq, *rk, *vm, *vc, *om, *oc;
    cudaGetSymbolAddress((void**)&Q128, g_Q128);
    cudaGetSymbolAddress((void**)&K128, g_K128);
    cudaGetSymbolAddress((void**)&rq,   g_rq);
    cudaGetSymbolAddress((void**)&rk,   g_rk);
    cudaGetSymbolAddress((void**)&vm,   g_vm);
    cudaGetSymbolAddress((void**)&vc,   g_vc);
    cudaGetSymbolAddress((void**)&om,   g_om);
    cudaGetSymbolAddress((void**)&oc,   g_oc);

    dim3 gb(128, 8), tb(256);
    // input projections (qk mean writes r, qk cov adds to r -> order matters)
    proj_gemm<M_QKMEAN><<<gb, tb>>>(q_mean, Wk_mean, bk_mean, Q128, rq);
    proj_gemm<M_QKCOV ><<<gb, tb>>>(q_cov,  Wk_cov,  bk_cov,  Q128, rq);
    proj_gemm<M_QKMEAN><<<gb, tb>>>(k_mean, Wk_mean, bk_mean, K128, rk);
    proj_gemm<M_QKCOV ><<<gb, tb>>>(k_cov,  Wk_cov,  bk_cov,  K128, rk);
    proj_gemm<M_V     ><<<gb, tb>>>(v_mean, Wv_mean, bv_mean, vm, nullptr);
    proj_gemm<M_V     ><<<gb, tb>>>(v_cov,  Wv_cov,  bv_cov,  vc, nullptr);

    const int smem = (32 * 129 + 8 * 128 + 8 * 1024) * 4;   // 53376 B
    cudaFuncSetAttribute(attn_kernel, cudaFuncAttributeMaxDynamicSharedMemorySize, smem);
    attn_kernel<<<dim3(64, 128), 256, smem>>>(gammas, zp);

    // output projections: d_out = [out_mean | out_cov]
    proj_gemm<M_PLAIN><<<gb, tb>>>(om, Wo_mean, bo_mean, out, nullptr);
    proj_gemm<M_PLAIN><<<gb, tb>>>(oc, Wo_cov,  bo_cov,  out + (size_t)BT_ * D_, nullptr);
}

// round 9
// speedup vs baseline: 1.2941x; 1.2941x over previous
#include <cuda_runtime.h>
#include <math.h>

#define B_ 8
#define T_ 1024
#define D_ 512
#define H_ 8
#define BT_ (B_*T_)        /* 8192  */
#define BHT_ (B_*H_*T_)    /* 65536 */

// ---------------- scratch (static device arrays: sanctioned no-alloc workaround) ----
__device__ float g_Q128[(size_t)BHT_*128];
__device__ float g_K128[(size_t)BHT_*128];
__device__ float g_rq[BHT_];
__device__ float g_rk[BHT_];
__device__ float g_vm[(size_t)BHT_*64];
__device__ float g_vc[(size_t)BHT_*64];
__device__ float g_om[(size_t)BT_*D_];
__device__ float g_oc[(size_t)BT_*D_];

enum { M_PLAIN = 0, M_QKMEAN = 1, M_QKCOV = 2, M_V = 3 };

// ---------------------------------------------------------------------------
// SGEMM: Y[m,n] = sum_k X[m,k]*W[n,k] + bias[n].  M=8192,N=512,K=512.
// BM=BN=128, BK=16, 256 threads, 8x8 per thread (2x2 blocks of 4x4).
// Warp = 32 rows x 64 cols; lanes 4x8; frag LDS.128 conflict-free.
// ---------------------------------------------------------------------------
template <int MODE>
__global__ __launch_bounds__(256) void proj_gemm(
    const float* __restrict__ X, const float* __restrict__ W,
    const float* __restrict__ bias, float* __restrict__ out,
    float* __restrict__ rbuf)
{
    __shared__ __align__(16) float As[16][132];
    __shared__ __align__(16) float Bs[16][132];

    const int tid  = threadIdx.x;
    const int w    = tid >> 5, lane = tid & 31;
    const int wr   = w >> 1,  wc   = w & 1;
    const int lr   = lane >> 3, lc = lane & 7;
    const int r0   = wr * 32 + lr * 4;   // rows r0..r0+3, r0+16..r0+19
    const int c0   = wc * 64 + lc * 4;   // cols c0..c0+3, c0+32..c0+35

    const int m0 = blockIdx.x * 128, n0 = blockIdx.y * 128;

    // staging map: thread loads rows sm_, sm_+64 at k-offset sk_ (float4)
    const int sm_ = tid >> 2;            // 0..63
    const int sk_ = (tid & 3) * 4;       // 0,4,8,12

    const float* Xb = X + (size_t)m0 * 512;
    const float* Wb = W + (size_t)n0 * 512;

    float4 xa0 = *(const float4*)(Xb + (size_t)sm_ * 512 + sk_);
    float4 xa1 = *(const float4*)(Xb + (size_t)(sm_ + 64) * 512 + sk_);
    float4 wa0 = *(const float4*)(Wb + (size_t)sm_ * 512 + sk_);
    float4 wa1 = *(const float4*)(Wb + (size_t)(sm_ + 64) * 512 + sk_);

    float acc[8][8];
#pragma unroll
    for (int i = 0; i < 8; i++)
#pragma unroll
        for (int j = 0; j < 8; j++) acc[i][j] = 0.f;

    for (int k0 = 0; k0 < 512; k0 += 16) {
        As[sk_+0][sm_]    = xa0.x; As[sk_+1][sm_]    = xa0.y; As[sk_+2][sm_]    = xa0.z; As[sk_+3][sm_]    = xa0.w;
        As[sk_+0][sm_+64] = xa1.x; As[sk_+1][sm_+64] = xa1.y; As[sk_+2][sm_+64] = xa1.z; As[sk_+3][sm_+64] = xa1.w;
        Bs[sk_+0][sm_]    = wa0.x; Bs[sk_+1][sm_]    = wa0.y; Bs[sk_+2][sm_]    = wa0.z; Bs[sk_+3][sm_]    = wa0.w;
        Bs[sk_+0][sm_+64] = wa1.x; Bs[sk_+1][sm_+64] = wa1.y; Bs[sk_+2][sm_+64] = wa1.z; Bs[sk_+3][sm_+64] = wa1.w;
        __syncthreads();
        if (k0 + 16 < 512) {
            const int kn = k0 + 16;
            xa0 = *(const float4*)(Xb + (size_t)sm_ * 512 + kn + sk_);
            xa1 = *(const float4*)(Xb + (size_t)(sm_ + 64) * 512 + kn + sk_);
            wa0 = *(const float4*)(Wb + (size_t)sm_ * 512 + kn + sk_);
            wa1 = *(const float4*)(Wb + (size_t)(sm_ + 64) * 512 + kn + sk_);
        }
#pragma unroll
        for (int k = 0; k < 16; k++) {
            float4 a0 = *(const float4*)(&As[k][r0]);
            float4 a1 = *(const float4*)(&As[k][r0 + 16]);
            float4 b0 = *(const float4*)(&Bs[k][c0]);
            float4 b1 = *(const float4*)(&Bs[k][c0 + 32]);
            float av[8] = {a0.x,a0.y,a0.z,a0.w, a1.x,a1.y,a1.z,a1.w};
            float bv[8] = {b0.x,b0.y,b0.z,b0.w, b1.x,b1.y,b1.z,b1.w};
#pragma unroll
            for (int i = 0; i < 8; i++)
#pragma unroll
                for (int j = 0; j < 8; j++)
                    acc[i][j] = fmaf(av[i], bv[j], acc[i][j]);
        }
        __syncthreads();
    }

    float bsv[8];
#pragma unroll
    for (int j = 0; j < 8; j++)
        bsv[j] = bias[n0 + c0 + (j & 3) + (j >> 2) * 32];

    const int head = (n0 + c0) >> 6;
    const int cih  = c0 & 63;           // cih, cih+32 both inside the 64-wide head
    float part[8];
#pragma unroll
    for (int i = 0; i < 8; i++) part[i] = 0.f;

#pragma unroll
    for (int i = 0; i < 8; i++) {
        const int row = r0 + (i & 3) + (i >> 2) * 16;
        const int m = m0 + row;
        const int bb = m >> 10, tt = m & 1023;
        const int bhh = bb * 8 + head;
        float y[8];
#pragma unroll
        for (int j = 0; j < 8; j++) y[j] = acc[i][j] + bsv[j];

        if (MODE == M_PLAIN) {
            *(float4*)(out + (size_t)m * 512 + n0 + c0)      = make_float4(y[0],y[1],y[2],y[3]);
            *(float4*)(out + (size_t)m * 512 + n0 + c0 + 32) = make_float4(y[4],y[5],y[6],y[7]);
        } else if (MODE == M_V) {
            const size_t base = ((size_t)bhh * 1024 + tt) * 64;
            *(float4*)(out + base + cih)      = make_float4(y[0],y[1],y[2],y[3]);
            *(float4*)(out + base + cih + 32) = make_float4(y[4],y[5],y[6],y[7]);
        } else if (MODE == M_QKMEAN) {
            const size_t base = ((size_t)bhh * 1024 + tt) * 128;
            *(float4*)(out + base + cih)      = make_float4(y[0],y[1],y[2],y[3]);
            *(float4*)(out + base + cih + 32) = make_float4(y[4],y[5],y[6],y[7]);
#pragma unroll
            for (int j = 0; j < 8; j++) part[i] += y[j] * y[j];
        } else { // M_QKCOV
            const size_t base = ((size_t)bhh * 1024 + tt) * 128 + 64;
            float s[8];
#pragma unroll
            for (int j = 0; j < 8; j++) s[j] = sqrtf(fmaxf(y[j], 1e-24f));
            *(float4*)(out + base + cih)      = make_float4(s[0],s[1],s[2],s[3]);
            *(float4*)(out + base + cih + 32) = make_float4(s[4],s[5],s[6],s[7]);
#pragma unroll
            for (int j = 0; j < 8; j++) part[i] += y[j];
        }
    }

    if (MODE == M_QKMEAN || MODE == M_QKCOV) {
        float* red = &As[0][0];              // 2112 floats >= 128*16
#pragma unroll
        for (int i = 0; i < 8; i++) {
            const int row = r0 + (i & 3) + (i >> 2) * 16;
            red[row * 16 + wc * 8 + lc] = part[i];
        }
        __syncthreads();
        {
            const int row = tid & 127, half = tid >> 7;   // 256 threads: 128 rows x 2 heads
            float ssum = 0.f;
#pragma unroll
            for (int x = 0; x < 8; x++) ssum += red[row * 16 + half * 8 + x];
            const int m = m0 + row;
            const int bb = m >> 10, tt = m & 1023;
            const int hh = (n0 >> 6) + half;
            const size_t idx = ((size_t)(bb * 8 + hh)) * 1024 + tt;
            if (MODE == M_QKMEAN) rbuf[idx] = ssum;
            else                  rbuf[idx] += ssum;
        }
    }
}

// ---------------------------------------------------------------------------
// Attention: block = (bh, 8 rows). P1: warps compute 4rowx8col score tiles
// (K float4 multicast across rows). P2-P4: warp-per-row softmax/rescore.
// P5: warps accumulate 4 rows x own-dims with V float4 reuse, smem reduce.
// ---------------------------------------------------------------------------
__global__ __launch_bounds__(256) void attn_kernel(const float* __restrict__ gammas,
                                                   const int* __restrict__ zp_ptr)
{
    extern __shared__ __align__(16) float smem_[];
    float* sTile = smem_;                 // 32*132
    float* sQ    = smem_ + 4224;          // 8*132
    float* sRow  = smem_ + 5280;          // 8*1024 (later: reduction scratch)
    float* sRq   = smem_ + 13472;         // 8
    float* sRk   = smem_ + 13480;         // 32
    float* sInv  = smem_ + 13512;         // 8

    const int bh   = blockIdx.x;
    const int b    = bh >> 3, h = bh & 7;
    const int w    = threadIdx.x >> 5, lane = threadIdx.x & 31;
    const int tbase = blockIdx.y * 8;
    const int ntiles = ((tbase + 7) >> 5) + 1;
    const int send = ntiles * 32;

    // stage q rows (stride 132) + rq
    for (int v = threadIdx.x; v < 1024; v += 256)
        sQ[(v >> 7) * 132 + (v & 127)] =
            g_Q128[((size_t)bh * T_ + tbase + (v >> 7)) * 128 + (v & 127)];
    if (threadIdx.x < 8)
        sRq[threadIdx.x] = g_rq[(size_t)bh * T_ + tbase + threadIdx.x];

    // ---- P1: scores. warp tile: rows rloc (4), cols sloc (8) -------------
    const int rloc = ((w & 1) << 2) | (lane >> 3);
    const int sloc = ((w >> 1) << 3) | (lane & 7);
    const float* qp = sQ + rloc * 132;
    const float* kp = sTile + sloc * 132;

    const float* Kg = g_K128 + (size_t)bh * T_ * 128;
    for (int it = 0; it < ntiles; ++it) {
        const int s0 = it * 32;
        for (int v = threadIdx.x; v < 1024; v += 256) {
            const int sr = v >> 5, c4 = (v & 31) * 4;
            float4 kv = *(const float4*)(Kg + (size_t)(s0 + sr) * 128 + c4);
            float* d = sTile + sr * 132 + c4;
            d[0]=kv.x; d[1]=kv.y; d[2]=kv.z; d[3]=kv.w;
        }
        if (threadIdx.x < 32)
            sRk[threadIdx.x] = g_rk[(size_t)bh * T_ + s0 + threadIdx.x];
        __syncthreads();

        float a0=0.f, a1=0.f, a2=0.f, a3=0.f;
#pragma unroll
        for (int c = 0; c < 128; c += 16) {
            float4 qA = *(const float4*)(qp + c);      float4 kA = *(const float4*)(kp + c);
            float4 qB = *(const float4*)(qp + c + 4);  float4 kB = *(const float4*)(kp + c + 4);
            float4 qC = *(const float4*)(qp + c + 8);  float4 kC = *(const float4*)(kp + c + 8);
            float4 qD = *(const float4*)(qp + c + 12); float4 kD = *(const float4*)(kp + c + 12);
            a0 = fmaf(qA.x,kA.x,a0); a0 = fmaf(qA.y,kA.y,a0); a0 = fmaf(qA.z,kA.z,a0); a0 = fmaf(qA.w,kA.w,a0);
            a1 = fmaf(qB.x,kB.x,a1); a1 = fmaf(qB.y,kB.y,a1); a1 = fmaf(qB.z,kB.z,a1); a1 = fmaf(qB.w,kB.w,a1);
            a2 = fmaf(qC.x,kC.x,a2); a2 = fmaf(qC.y,kC.y,a2); a2 = fmaf(qC.z,kC.z,a2); a2 = fmaf(qC.w,kC.w,a2);
            a3 = fmaf(qD.x,kD.x,a3); a3 = fmaf(qD.y,kD.y,a3); a3 = fmaf(qD.z,kD.z,a3); a3 = fmaf(qD.w,kD.w,a3);
        }
        const float dot = (a0 + a1) + (a2 + a3);
        sRow[rloc * 1024 + s0 + sloc] = (2.f * dot - sRq[rloc] - sRk[sloc]) * 0.125f;
        __syncthreads();
    }

    // ---- P2-P4: warp-per-row ---------------------------------------------
    const int t = tbase + w;
    float* row = sRow + w * 1024;
    const float g  = gammas[h];
    const float sp = (g > 20.f) ? g : log1pf(__expf(g));
    const float gamma = -sp;

    // P2: first softmax max + denom
    float m1 = -3.4e38f;
    for (int s = lane; s <= t; s += 32) m1 = fmaxf(m1, row[s]);
#pragma unroll
    for (int o = 16; o; o >>= 1) m1 = fmaxf(m1, __shfl_xor_sync(0xffffffffu, m1, o));
    float den1 = 0.f;
    for (int s = lane; s <= t; s += 32) den1 += __expf(row[s] - m1);
#pragma unroll
    for (int o = 16; o; o >>= 1) den1 += __shfl_xor_sync(0xffffffffu, den1, o);
    const float inv1 = 1.f / den1;

    // P3: cumsum + position-decay rescore
    float carry = 0.f, m2 = -3.4e38f;
    for (int s0 = 0; s0 <= t; s0 += 32) {
        const int s = s0 + lane;
        const bool valid = (s <= t);
        const float sc = valid ? row[s] : 0.f;
        const float e  = valid ? __expf(sc - m1) : 0.f;
        float x = e;
#pragma unroll
        for (int d = 1; d < 32; d <<= 1) {
            float y = __shfl_up_sync(0xffffffffu, x, d);
            if (lane >= d) x += y;
        }
        const float tot = __shfl_sync(0xffffffffu, x, 31);
        const float cum = carry + x;
        carry += tot;
        if (valid) {
            const float tail = (den1 - cum) * inv1;
            const float pos  = (float)(t - s);
            const float dsc  = sqrtf(fmaxf(tail * pos, 0.f));
            float eff = __expf(gamma * dsc);
            eff = fminf(fmaxf(eff, 1e-5f), 1e5f);
            const float ns = sc * eff;
            row[s] = ns;
            m2 = fmaxf(m2, ns);
        }
    }
#pragma unroll
    for (int o = 16; o; o >>= 1) m2 = fmaxf(m2, __shfl_xor_sync(0xffffffffu, m2, o));

    // P4: second softmax; store exp in place; zero the rest of the row
    float den2 = 0.f;
    for (int s0 = 0; s0 <= t; s0 += 32) {
        const int s = s0 + lane;
        const float e = (s <= t) ? __expf(row[s] - m2) : 0.f;
        row[s] = e;
        den2 += e;
    }
#pragma unroll
    for (int o = 16; o; o >>= 1) den2 += __shfl_xor_sync(0xffffffffu, den2, o);
    for (int s = t + 1 + lane; s < send; s += 32) row[s] = 0.f;   // P5 reads unguarded
    if (lane == 0) sInv[w] = 1.f / den2;
    __syncthreads();

    // ---- P5: warp = 4 rows x (own 4 dims), s split over 4 warp groups ----
    const int rb  = (w & 1) * 4;       // row group
    const int sq8 = (w >> 1) * 8;      // s offset inside tile
    float pacc[4][4];
#pragma unroll
    for (int r = 0; r < 4; r++)
#pragma unroll
        for (int q = 0; q < 4; q++) pacc[r][q] = 0.f;

    const float* Vm = g_vm + (size_t)bh * T_ * 64;
    const float* Vc = g_vc + (size_t)bh * T_ * 64;
    const int d4 = lane * 4;           // concat dim: <64 mean, >=64 cov

    for (int it = 0; it < ntiles; ++it) {
        const int s0 = it * 32;
        for (int v = threadIdx.x; v < 1024; v += 256) {
            const int sr = v >> 5, c4 = (v & 31) * 4;
            float4 val = (c4 < 64)
                ? *(const float4*)(Vm + (size_t)(s0 + sr) * 64 + c4)
                : *(const float4*)(Vc + (size_t)(s0 + sr) * 64 + (c4 - 64));
            float* d = sTile + sr * 132 + c4;
            d[0]=val.x; d[1]=val.y; d[2]=val.z; d[3]=val.w;
        }
        __syncthreads();
#pragma unroll
        for (int jj = 0; jj < 8; jj++) {
            const int j = sq8 + jj;
            const float4 v4 = *(const float4*)(sTile + j * 132 + d4);
#pragma unroll
            for (int r = 0; r < 4; r++) {
                const float e = sRow[(rb + r) * 1024 + s0 + j];
                const float mlt = (d4 < 64) ? e : e * e;
                pacc[r][0] = fmaf(mlt, v4.x, pacc[r][0]);
                pacc[r][1] = fmaf(mlt, v4.y, pacc[r][1]);
                pacc[r][2] = fmaf(mlt, v4.z, pacc[r][2]);
                pacc[r][3] = fmaf(mlt, v4.w, pacc[r][3]);
            }
        }
        __syncthreads();
    }

    // partial store (reuse sRow; probs fully consumed) + tree reduce
    const int pp = w >> 1;
#pragma unroll
    for (int r = 0; r < 4; r++)
        *(float4*)(sRow + pp * 1024 + (rb + r) * 128 + d4) =
            make_float4(pacc[r][0], pacc[r][1], pacc[r][2], pacc[r][3]);
    __syncthreads();

    {
        const int rr = threadIdx.x >> 5;          // 0..7
        const int dd = (threadIdx.x & 31) * 4;    // 0..124
        float4 p0 = *(const float4*)(sRow + 0 * 1024 + rr * 128 + dd);
        float4 p1 = *(const float4*)(sRow + 1 * 1024 + rr * 128 + dd);
        float4 p2 = *(const float4*)(sRow + 2 * 1024 + rr * 128 + dd);
        float4 p3 = *(const float4*)(sRow + 3 * 1024 + rr * 128 + dd);
        const int tt = tbase + rr;
        const float i2 = sInv[rr];
        float scale = (dd < 64) ? i2 : i2 * i2;
        if (tt == 0 && (*zp_ptr)) scale = 0.f;
        float4 res = make_float4((p0.x+p1.x+p2.x+p3.x) * scale,
                                 (p0.y+p1.y+p2.y+p3.y) * scale,
                                 (p0.z+p1.z+p2.z+p3.z) * scale,
                                 (p0.w+p1.w+p2.w+p3.w) * scale);
        const size_t ob = ((size_t)b * 1024 + tt) * 512 + h * 64;
        if (dd < 64) *(float4*)(g_om + ob + dd)      = res;
        else         *(float4*)(g_oc + ob + dd - 64) = res;
    }
}

// ---------------------------------------------------------------------------
extern "C" void kernel_launch(void* const* d_in, const int* in_sizes, int n_in,
                              void* d_out, int out_size)
{
    const float* q_mean  = (const float*)d_in[0];
    const float* q_cov   = (const float*)d_in[1];
    const float* k_mean  = (const float*)d_in[2];
    const float* k_cov   = (const float*)d_in[3];
    const float* v_mean  = (const float*)d_in[4];
    const float* v_cov   = (const float*)d_in[5];
    const float* Wk_mean = (const float*)d_in[6];
    const float* bk_mean = (const float*)d_in[7];
    const float* Wk_cov  = (const float*)d_in[8];
    const float* bk_cov  = (const float*)d_in[9];
    const float* Wv_mean = (const float*)d_in[10];
    const float* bv_mean = (const float*)d_in[11];
    const float* Wv_cov  = (const float*)d_in[12];
    const float* bv_cov  = (const float*)d_in[13];
    const float* Wo_mean = (const float*)d_in[14];
    const float* bo_mean = (const float*)d_in[15];
    const float* Wo_cov  = (const float*)d_in[16];
    const float* bo_cov  = (const float*)d_in[17];
    const float* gammas  = (const float*)d_in[18];
    const int*   zp      = (const int*)d_in[20];
    float* out = (float*)d_out;

    float *Q128, *K128, *rq, *rk, *vm, *vc, *om, *oc;
    cudaGetSymbolAddress((void**)&Q128, g_Q128);
    cudaGetSymbolAddress((void**)&K128, g_K128);
    cudaGetSymbolAddress((void**)&rq,   g_rq);
    cudaGetSymbolAddress((void**)&rk,   g_rk);
    cudaGetSymbolAddress((void**)&vm,   g_vm);
    cudaGetSymbolAddress((void**)&vc,   g_vc);
    cudaGetSymbolAddress((void**)&om,   g_om);
    cudaGetSymbolAddress((void**)&oc,   g_oc);

    dim3 gb(64, 4), tb(256);
    // input projections (qk mean writes rbuf, qk cov accumulates -> order matters)
    proj_gemm<M_QKMEAN><<<gb, tb>>>(q_mean, Wk_mean, bk_mean, Q128, rq);
    proj_gemm<M_QKCOV ><<<gb, tb>>>(q_cov,  Wk_cov,  bk_cov,  Q128, rq);
    proj_gemm<M_QKMEAN><<<gb, tb>>>(k_mean, Wk_mean, bk_mean, K128, rk);
    proj_gemm<M_QKCOV ><<<gb, tb>>>(k_cov,  Wk_cov,  bk_cov,  K128, rk);
    proj_gemm<M_V     ><<<gb, tb>>>(v_mean, Wv_mean, bv_mean, vm, nullptr);
    proj_gemm<M_V     ><<<gb, tb>>>(v_cov,  Wv_cov,  bv_cov,  vc, nullptr);

    const int smem = 13520 * 4;   // 54080 B
    cudaFuncSetAttribute(attn_kernel, cudaFuncAttributeMaxDynamicSharedMemorySize, smem);
    attn_kernel<<<dim3(64, 128), 256, smem>>>(gammas, zp);

    // output projections: d_out = [out_mean | out_cov]
    proj_gemm<M_PLAIN><<<gb, tb>>>(om, Wo_mean, bo_mean, out, nullptr);
    proj_gemm<M_PLAIN><<<gb, tb>>>(oc, Wo_cov,  bo_cov,  out + (size_t)BT_ * D_, nullptr);
}